// round 10
// baseline (speedup 1.0000x reference)
#include <cuda_runtime.h>
#include <cuda_fp16.h>
#include <cstdint>
#include <cstddef>

#define HID 128
#define C3  384
#define TT  512
#define BB  4096
#define INP 28

// 3.2 GB scratch: gx[t][b][c], c = g*128+u. Split in halves by t.
__device__ __align__(16) float g_gx_lo[(size_t)256 * BB * C3];
__device__ __align__(16) float g_gx_hi[(size_t)256 * BB * C3];

// Packed dual-fp32 FMA
static __device__ __forceinline__ float2 ffma2(float2 a, float2 b, float2 c) {
    unsigned long long ua, ub, uc, ud;
    ua = *reinterpret_cast<unsigned long long*>(&a);
    ub = *reinterpret_cast<unsigned long long*>(&b);
    uc = *reinterpret_cast<unsigned long long*>(&c);
    asm("fma.rn.f32x2 %0, %1, %2, %3;" : "=l"(ud) : "l"(ua), "l"(ub), "l"(uc));
    return *reinterpret_cast<float2*>(&ud);
}
static __device__ __forceinline__ float sig1(float x) {
    float e = __expf(-x);
    return __fdividef(1.0f, 1.0f + e);
}
static __device__ __forceinline__ float tanh1(float x) {
    float e = __expf(2.0f * x);
    return 1.0f - __fdividef(2.0f, e + 1.0f);
}

static __device__ __forceinline__ uint32_t smem_u32(const void* p) {
    uint32_t a;
    asm("{ .reg .u64 t; cvta.to.shared.u64 t, %1; cvt.u32.u64 %0, t; }"
        : "=r"(a) : "l"(p));
    return a;
}
static __device__ __forceinline__ void ldsm4(uint32_t& r0, uint32_t& r1,
                                             uint32_t& r2, uint32_t& r3, uint32_t a) {
    asm volatile("ldmatrix.sync.aligned.m8n8.x4.shared.b16 {%0,%1,%2,%3}, [%4];"
                 : "=r"(r0), "=r"(r1), "=r"(r2), "=r"(r3) : "r"(a));
}
static __device__ __forceinline__ void ldsm4t(uint32_t& r0, uint32_t& r1,
                                              uint32_t& r2, uint32_t& r3, uint32_t a) {
    asm volatile("ldmatrix.sync.aligned.m8n8.x4.trans.shared.b16 {%0,%1,%2,%3}, [%4];"
                 : "=r"(r0), "=r"(r1), "=r"(r2), "=r"(r3) : "r"(a));
}
static __device__ __forceinline__ void mma16816(float* d,
        uint32_t a0, uint32_t a1, uint32_t a2, uint32_t a3,
        uint32_t b0, uint32_t b1) {
    asm volatile("mma.sync.aligned.m16n8k16.row.col.f32.f16.f16.f32 "
                 "{%0,%1,%2,%3},{%4,%5,%6,%7},{%8,%9},{%0,%1,%2,%3};"
                 : "+f"(d[0]), "+f"(d[1]), "+f"(d[2]), "+f"(d[3])
                 : "r"(a0), "r"(a1), "r"(a2), "r"(a3), "r"(b0), "r"(b1));
}

// ---------------------------------------------------------------------------
// Kernel A: unchanged (passing, ~1.19 ms)
// ---------------------------------------------------------------------------
__global__ void __launch_bounds__(384, 2)
gx_kernel(const float* __restrict__ x,
          const float* __restrict__ w_x,
          const float* __restrict__ b_x) {
    extern __shared__ float sm[];
    float* sWx = sm;
    float* sXt = sm + INP * C3;

    const int b   = blockIdx.x;
    const int tid = threadIdx.x;

    for (int idx = tid; idx < INP * C3; idx += 384) {
        int k = idx / C3, c = idx % C3;
        sWx[idx] = w_x[(size_t)(c >> 7) * INP * HID + k * HID + (c & 127)];
    }

    const int cg = tid % 96;
    const int rg = tid / 96;
    const int c0 = 4 * cg;

    float2 bx0 = *(const float2*)(b_x + c0);
    float2 bx1 = *(const float2*)(b_x + c0 + 2);
    float bxs[4] = {bx0.x, bx0.y, bx1.x, bx1.y};

    for (int tc = 0; tc < 16; ++tc) {
        const int t0 = 32 * tc;
        __syncthreads();
        const float* xg = x + ((size_t)b * TT + t0) * INP;
        for (int idx = tid; idx < 32 * INP; idx += 384) {
            int tt = idx / INP, k = idx % INP;
            sXt[k * 32 + tt] = xg[idx];
        }
        __syncthreads();

        float2 a[4][4];
#pragma unroll
        for (int p = 0; p < 4; ++p)
#pragma unroll
            for (int c = 0; c < 4; ++c) a[p][c] = make_float2(0.f, 0.f);

        const float* xp0 = sXt + rg * 8;
        const float* wp0 = sWx + c0;

#pragma unroll 7
        for (int k = 0; k < INP; ++k) {
            float4 wv = *(const float4*)(wp0 + k * C3);
            float2 wc[4];
            wc[0] = make_float2(wv.x, wv.x);
            wc[1] = make_float2(wv.y, wv.y);
            wc[2] = make_float2(wv.z, wv.z);
            wc[3] = make_float2(wv.w, wv.w);
            const float* xp = xp0 + k * 32;
            float4 xa = *(const float4*)(xp);
            float4 xb = *(const float4*)(xp + 4);
            float2 hp[4];
            hp[0] = make_float2(xa.x, xa.y); hp[1] = make_float2(xa.z, xa.w);
            hp[2] = make_float2(xb.x, xb.y); hp[3] = make_float2(xb.z, xb.w);
#pragma unroll
            for (int p = 0; p < 4; ++p) {
#pragma unroll
                for (int c = 0; c < 4; ++c)
                    a[p][c] = ffma2(hp[p], wc[c], a[p][c]);
            }
        }

#pragma unroll
        for (int r = 0; r < 8; ++r) {
            int p = r >> 1, q = r & 1;
            int t = t0 + rg * 8 + r;
            float* base = (t < 256) ? g_gx_lo : g_gx_hi;
            float v0 = (q ? a[p][0].y : a[p][0].x) + bxs[0];
            float v1 = (q ? a[p][1].y : a[p][1].x) + bxs[1];
            float v2 = (q ? a[p][2].y : a[p][2].x) + bxs[2];
            float v3 = (q ? a[p][3].y : a[p][3].x) + bxs[3];
            *(float4*)(base + ((size_t)(t & 255) * BB + b) * C3 + c0) =
                make_float4(v0, v1, v2, v3);
        }
    }
}

// ---------------------------------------------------------------------------
// Kernel B: GRU on HMMA (3-term fp16 split), now 512 threads / 16 warps
// (4 per SMSP) for latency hiding. Warp w (0..7): units 16w, batch 0..15;
// warp w+8: units 16w, batch 16..31. Per warp: 3 gates x 2 nb x 3 terms x
// 8 kt = 144 mma/step. Gates thread-local (8 elems/thread).
// ---------------------------------------------------------------------------
#define ASTR 136                    // A row stride (halfs), ldsm conflict-free
#define AMAT (HID * ASTR)
#define BSTR 40                     // B row stride (halfs), ldsm.t conflict-free
#define SM_B0 (6 * AMAT * 2)        // 208896
#define SM_B1 (SM_B0 + HID * BSTR * 2)
#define SM_TOT (SM_B1 + HID * BSTR * 2)   // 229376

__global__ void __launch_bounds__(512, 1)
gru_kernel(const float* __restrict__ w_h,
           const float* __restrict__ b_h,
           const float* __restrict__ fc_w,
           const float* __restrict__ fc_b,
           float* __restrict__ out) {
    extern __shared__ char smem[];
    __half* sA = (__half*)smem;
    __half* sBhh = (__half*)(smem + SM_B0);
    __half* sBhl = (__half*)(smem + SM_B1);
    const uint32_t sb = smem_u32(smem);

    const int tid = threadIdx.x;
    const int w   = tid >> 5;
    const int L   = tid & 31;
    const int uw  = w & 7;            // unit-group warp index
    const int bhalf = (w >> 3) * 16;  // batch half offset
    const int row0 = blockIdx.x * 32;
    const int uBase = 16 * uw + (L >> 2);

    // ---- load + split weights into A matrices (once) ----
    for (int g = 0; g < 3; ++g) {
        __half* ah = sA + (g * 2 + 0) * AMAT;
        __half* al = sA + (g * 2 + 1) * AMAT;
        const float* wg = w_h + (size_t)g * HID * HID;
        for (int idx = tid; idx < HID * HID; idx += 512) {
            int k = idx >> 7, u = idx & 127;
            float v = wg[idx];
            __half hi = __float2half_rn(v);
            __half lo = __float2half_rn(v - __half2float(hi));
            ah[u * ASTR + k] = hi;
            al[u * ASTR + k] = lo;
        }
    }
    for (int i = tid; i < HID * BSTR; i += 512) {
        sBhh[i] = __ushort_as_half(0);
        sBhl[i] = __ushort_as_half(0);
    }
    __syncthreads();

    // ---- lane-constant ldmatrix addresses ----
    const uint32_t lrow = (L & 7) + ((L >> 3) & 1) * 8;
    const uint32_t lcol = (L >> 4) * 8;
    uint32_t aAddr[6];
#pragma unroll
    for (int m = 0; m < 6; ++m)
        aAddr[m] = sb + (uint32_t)(m * AMAT + (16 * uw + lrow) * ASTR + lcol) * 2;
    const uint32_t bAddrHH = sb + SM_B0 + (lrow * BSTR + lcol + bhalf) * 2;
    const uint32_t bAddrHL = sb + SM_B1 + (lrow * BSTR + lcol + bhalf) * 2;

    // ---- biases, state ----
    float bhr[2], bhz[2], bhn[2];
#pragma unroll
    for (int ui = 0; ui < 2; ++ui) {
        int u = uBase + 8 * ui;
        bhr[ui] = b_h[u];
        bhz[ui] = b_h[HID + u];
        bhn[ui] = b_h[2 * HID + u];
    }
    float hold[2][4];
#pragma unroll
    for (int ui = 0; ui < 2; ++ui)
#pragma unroll
        for (int e = 0; e < 4; ++e) hold[ui][e] = 0.0f;

    for (int t = 0; t < TT; ++t) {
        // ---- prefetch gx(t): e = 2*nb + q -> batch bhalf + 8nb + 2(L%4)+q ----
        float pg[3][2][4];
        {
            const float* base = (t < 256) ? g_gx_lo : g_gx_hi;
            const float* gp = base + (size_t)(t & 255) * BB * C3;
#pragma unroll
            for (int g = 0; g < 3; ++g)
#pragma unroll
                for (int ui = 0; ui < 2; ++ui) {
                    int u = uBase + 8 * ui;
#pragma unroll
                    for (int e = 0; e < 4; ++e) {
                        int b = bhalf + 8 * (e >> 1) + 2 * (L & 3) + (e & 1);
                        pg[g][ui][e] = __ldg(gp + (size_t)(row0 + b) * C3 + g * HID + u);
                    }
                }
        }

        // ---- MMA ----
        float acc[3][2][4];
#pragma unroll
        for (int g = 0; g < 3; ++g)
#pragma unroll
            for (int nb = 0; nb < 2; ++nb)
#pragma unroll
                for (int i = 0; i < 4; ++i) acc[g][nb][i] = 0.0f;

#pragma unroll 2
        for (int kt = 0; kt < 8; ++kt) {
            uint32_t bh[2][2], bl[2][2];
            {
                uint32_t r0, r1, r2, r3;
                ldsm4t(r0, r1, r2, r3, bAddrHH + kt * (16 * BSTR * 2));
                bh[0][0] = r0; bh[0][1] = r1; bh[1][0] = r2; bh[1][1] = r3;
                ldsm4t(r0, r1, r2, r3, bAddrHL + kt * (16 * BSTR * 2));
                bl[0][0] = r0; bl[0][1] = r1; bl[1][0] = r2; bl[1][1] = r3;
            }
#pragma unroll
            for (int g = 0; g < 3; ++g) {
                uint32_t ah0, ah1, ah2, ah3, al0, al1, al2, al3;
                ldsm4(ah0, ah1, ah2, ah3, aAddr[g * 2 + 0] + kt * 32);
                ldsm4(al0, al1, al2, al3, aAddr[g * 2 + 1] + kt * 32);
#pragma unroll
                for (int nb = 0; nb < 2; ++nb) {
                    mma16816(acc[g][nb], ah0, ah1, ah2, ah3, bh[nb][0], bh[nb][1]);
                    mma16816(acc[g][nb], ah0, ah1, ah2, ah3, bl[nb][0], bl[nb][1]);
                    mma16816(acc[g][nb], al0, al1, al2, al3, bh[nb][0], bh[nb][1]);
                }
            }
        }

        // ---- gates (thread-local) ----
        float hn[2][4];
#pragma unroll
        for (int ui = 0; ui < 2; ++ui)
#pragma unroll
            for (int nb = 0; nb < 2; ++nb)
#pragma unroll
                for (int q = 0; q < 2; ++q) {
                    int e = 2 * nb + q;
                    float ar = acc[0][nb][2 * ui + q] + pg[0][ui][e] + bhr[ui];
                    float az = acc[1][nb][2 * ui + q] + pg[1][ui][e] + bhz[ui];
                    float an = acc[2][nb][2 * ui + q] + bhn[ui];
                    float rr = sig1(ar);
                    float zz = sig1(az);
                    float nn = tanh1(pg[2][ui][e] + rr * an);
                    hn[ui][e] = nn + zz * (hold[ui][e] - nn);
                    hold[ui][e] = hn[ui][e];
                }

        __syncthreads();   // all warps done reading B(t)

        // ---- write h(t+1) hi/lo into B [k=unit][b] ----
#pragma unroll
        for (int ui = 0; ui < 2; ++ui) {
            int u = uBase + 8 * ui;
#pragma unroll
            for (int nb = 0; nb < 2; ++nb) {
                int b = bhalf + 8 * nb + 2 * (L & 3);
                float v0 = hn[ui][2 * nb], v1 = hn[ui][2 * nb + 1];
                __half h0 = __float2half_rn(v0);
                __half h1 = __float2half_rn(v1);
                __half l0 = __float2half_rn(v0 - __half2float(h0));
                __half l1 = __float2half_rn(v1 - __half2float(h1));
                *(__half2*)(sBhh + u * BSTR + b) = __halves2half2(h0, h1);
                *(__half2*)(sBhl + u * BSTR + b) = __halves2half2(l0, l1);
            }
        }
        __syncthreads();   // B(t+1) visible
    }

    // ---- FC epilogue ----
    float* sH  = (float*)smem;              // [128][33]
    float* sFW = (float*)smem + HID * 33;
#pragma unroll
    for (int ui = 0; ui < 2; ++ui) {
        int u = uBase + 8 * ui;
#pragma unroll
        for (int e = 0; e < 4; ++e) {
            int b = bhalf + 8 * (e >> 1) + 2 * (L & 3) + (e & 1);
            sH[u * 33 + b] = hold[ui][e];
        }
    }
    for (int i = tid; i < HID * 10; i += 512) sFW[i] = fc_w[i];
    __syncthreads();
    for (int i = tid; i < 32 * 10; i += 512) {
        int lr = i / 10, col = i % 10;
        float s = fc_b[col];
#pragma unroll 8
        for (int uu = 0; uu < HID; ++uu)
            s += sH[uu * 33 + lr] * sFW[uu * 10 + col];
        out[(size_t)(row0 + lr) * 10 + col] = s;
    }
}

extern "C" void kernel_launch(void* const* d_in, const int* in_sizes, int n_in,
                              void* d_out, int out_size) {
    const float* x    = (const float*)d_in[0];
    const float* w_x  = (const float*)d_in[1];
    const float* b_x  = (const float*)d_in[2];
    const float* w_h  = (const float*)d_in[3];
    const float* b_h  = (const float*)d_in[4];
    const float* fc_w = (const float*)d_in[5];
    const float* fc_b = (const float*)d_in[6];
    float* out = (float*)d_out;

    const int smemA = (INP * C3 + 32 * INP) * sizeof(float);
    cudaFuncSetAttribute(gx_kernel,  cudaFuncAttributeMaxDynamicSharedMemorySize, smemA);
    cudaFuncSetAttribute(gru_kernel, cudaFuncAttributeMaxDynamicSharedMemorySize, SM_TOT);

    gx_kernel<<<BB, 384, smemA>>>(x, w_x, b_x);
    gru_kernel<<<128, 512, SM_TOT>>>(w_h, b_h, fc_w, fc_b, out);
}

// round 11
// speedup vs baseline: 1.1464x; 1.1464x over previous
#include <cuda_runtime.h>
#include <cuda_fp16.h>
#include <cstdint>
#include <cstddef>

#define HID 128
#define C3  384
#define TT  512
#define BB  4096
#define INP 28

// 3.2 GB scratch: gx[t][b][c], c = g*128+u. Split in halves by t.
__device__ __align__(16) float g_gx_lo[(size_t)256 * BB * C3];
__device__ __align__(16) float g_gx_hi[(size_t)256 * BB * C3];

static __device__ __forceinline__ float sig1(float x) {
    float e = __expf(-x);
    return __fdividef(1.0f, 1.0f + e);
}
static __device__ __forceinline__ float tanh1(float x) {
    float e = __expf(2.0f * x);
    return 1.0f - __fdividef(2.0f, e + 1.0f);
}
static __device__ __forceinline__ uint32_t smem_u32(const void* p) {
    uint32_t a;
    asm("{ .reg .u64 t; cvta.to.shared.u64 t, %1; cvt.u32.u64 %0, t; }"
        : "=r"(a) : "l"(p));
    return a;
}
static __device__ __forceinline__ void ldsm4(uint32_t& r0, uint32_t& r1,
                                             uint32_t& r2, uint32_t& r3, uint32_t a) {
    asm volatile("ldmatrix.sync.aligned.m8n8.x4.shared.b16 {%0,%1,%2,%3}, [%4];"
                 : "=r"(r0), "=r"(r1), "=r"(r2), "=r"(r3) : "r"(a));
}
static __device__ __forceinline__ void ldsm4t(uint32_t& r0, uint32_t& r1,
                                              uint32_t& r2, uint32_t& r3, uint32_t a) {
    asm volatile("ldmatrix.sync.aligned.m8n8.x4.trans.shared.b16 {%0,%1,%2,%3}, [%4];"
                 : "=r"(r0), "=r"(r1), "=r"(r2), "=r"(r3) : "r"(a));
}
static __device__ __forceinline__ void mma16816(float* d,
        uint32_t a0, uint32_t a1, uint32_t a2, uint32_t a3,
        uint32_t b0, uint32_t b1) {
    asm volatile("mma.sync.aligned.m16n8k16.row.col.f32.f16.f16.f32 "
                 "{%0,%1,%2,%3},{%4,%5,%6,%7},{%8,%9},{%0,%1,%2,%3};"
                 : "+f"(d[0]), "+f"(d[1]), "+f"(d[2]), "+f"(d[3])
                 : "r"(a0), "r"(a1), "r"(a2), "r"(a3), "r"(b0), "r"(b1));
}

// ---------------------------------------------------------------------------
// Kernel A (HMMA): gx[t][b][c] = sum_k x[b][t][k] * w_x[k][c] + b_x[c]
// CTA = (bgroup of 128 rows, t). A = x hi/lo fp16 [128r][32k], B = w hi/lo
// [32k][384c]; 3-term split (xh*wh + xl*wh + xh*wl). 8 warps: warp w owns
// m-tile rows 16w, loops 6 n-chunks of 64. K padded 28->32 with zeros.
// ---------------------------------------------------------------------------
#define WSTR 392                    // w smem stride (halfs): 49k mod 8 distinct
#define XSTR 40                     // x smem stride (halfs): 5r mod 8 distinct
#define GSM_WH 0
#define GSM_WL (32 * WSTR * 2)                  // 25088
#define GSM_XH (GSM_WL + 32 * WSTR * 2)         // 50176
#define GSM_XL (GSM_XH + HID * XSTR * 2)        // 60416
#define GSM_BX (GSM_XL + HID * XSTR * 2)        // 70656
#define GSM_TOT (GSM_BX + C3 * 4)               // 72192

__global__ void __launch_bounds__(256, 2)
gx_kernel(const float* __restrict__ x,
          const float* __restrict__ w_x,
          const float* __restrict__ b_x) {
    extern __shared__ char smem[];
    __half* sWH = (__half*)(smem + GSM_WH);
    __half* sWL = (__half*)(smem + GSM_WL);
    __half* sXH = (__half*)(smem + GSM_XH);
    __half* sXL = (__half*)(smem + GSM_XL);
    float*  sBX = (float*)(smem + GSM_BX);
    const uint32_t sb = smem_u32(smem);

    const int tid = threadIdx.x;
    const int w   = tid >> 5;
    const int L   = tid & 31;
    const int b0  = blockIdx.x * 128;
    const int t   = blockIdx.y;

    // ---- w hi/lo into smem [k][c]; c = g*128 + u ----
    for (int idx = tid; idx < 3 * INP * HID; idx += 256) {
        int g = idx / (INP * HID);
        int k = (idx / HID) % INP;
        int u = idx & 127;
        float v = w_x[idx];
        __half hi = __float2half_rn(v);
        __half lo = __float2half_rn(v - __half2float(hi));
        sWH[k * WSTR + g * HID + u] = hi;
        sWL[k * WSTR + g * HID + u] = lo;
    }
    // zero k-pad rows 28..31 of w
    for (int idx = tid; idx < 4 * C3; idx += 256) {
        int k = 28 + idx / C3, c = idx % C3;
        sWH[k * WSTR + c] = __ushort_as_half(0);
        sWL[k * WSTR + c] = __ushort_as_half(0);
    }
    // ---- x hi/lo into smem [r][k] (float4 loads: 7 per row) ----
    for (int idx = tid; idx < 128 * 7; idx += 256) {
        int r = idx / 7, f = idx % 7;
        float4 v = *(const float4*)(x + ((size_t)(b0 + r) * TT + t) * INP + 4 * f);
        float vs[4] = {v.x, v.y, v.z, v.w};
#pragma unroll
        for (int j = 0; j < 4; ++j) {
            __half hi = __float2half_rn(vs[j]);
            __half lo = __float2half_rn(vs[j] - __half2float(hi));
            sXH[r * XSTR + 4 * f + j] = hi;
            sXL[r * XSTR + 4 * f + j] = lo;
        }
    }
    // zero k-pad cols 28..31 of x
    for (int idx = tid; idx < 128 * 4; idx += 256) {
        int r = idx >> 2, k = 28 + (idx & 3);
        sXH[r * XSTR + k] = __ushort_as_half(0);
        sXL[r * XSTR + k] = __ushort_as_half(0);
    }
    for (int i = tid; i < C3; i += 256) sBX[i] = b_x[i];
    __syncthreads();

    // ---- lane-constant ldmatrix addresses ----
    const uint32_t lrow = (L & 7) + ((L >> 3) & 1) * 8;
    const uint32_t lcol = (L >> 4) * 8;
    const uint32_t aXH = sb + GSM_XH + (uint32_t)((16 * w + lrow) * XSTR + lcol) * 2;
    const uint32_t aXL = sb + GSM_XL + (uint32_t)((16 * w + lrow) * XSTR + lcol) * 2;
    const uint32_t bWH = sb + GSM_WH + (uint32_t)(lrow * WSTR + lcol) * 2;
    const uint32_t bWL = sb + GSM_WL + (uint32_t)(lrow * WSTR + lcol) * 2;

    // ---- A fragments (register-resident, reused across all n-chunks) ----
    uint32_t axh[2][4], axl[2][4];
#pragma unroll
    for (int kt = 0; kt < 2; ++kt) {
        ldsm4(axh[kt][0], axh[kt][1], axh[kt][2], axh[kt][3], aXH + kt * 32);
        ldsm4(axl[kt][0], axl[kt][1], axl[kt][2], axl[kt][3], aXL + kt * 32);
    }

    float* gxo = ((t < 256) ? g_gx_lo : g_gx_hi) + (size_t)(t & 255) * BB * C3;
    const int rA = 16 * w + (L >> 2);
    const int cq = 2 * (L & 3);

#pragma unroll 1
    for (int ch = 0; ch < 6; ++ch) {
        float acc[8][4];
#pragma unroll
        for (int nb = 0; nb < 8; ++nb)
#pragma unroll
            for (int i = 0; i < 4; ++i) acc[nb][i] = 0.0f;

#pragma unroll
        for (int kt = 0; kt < 2; ++kt) {
#pragma unroll
            for (int grp = 0; grp < 4; ++grp) {
                uint32_t off = (uint32_t)(kt * 16 * WSTR + ch * 64 + grp * 16) * 2;
                uint32_t h0, h1, h2, h3, l0, l1, l2, l3;
                ldsm4t(h0, h1, h2, h3, bWH + off);
                ldsm4t(l0, l1, l2, l3, bWL + off);
                float* a0 = acc[2 * grp];
                float* a1 = acc[2 * grp + 1];
                mma16816(a0, axh[kt][0], axh[kt][1], axh[kt][2], axh[kt][3], h0, h1);
                mma16816(a0, axl[kt][0], axl[kt][1], axl[kt][2], axl[kt][3], h0, h1);
                mma16816(a0, axh[kt][0], axh[kt][1], axh[kt][2], axh[kt][3], l0, l1);
                mma16816(a1, axh[kt][0], axh[kt][1], axh[kt][2], axh[kt][3], h2, h3);
                mma16816(a1, axl[kt][0], axl[kt][1], axl[kt][2], axl[kt][3], h2, h3);
                mma16816(a1, axh[kt][0], axh[kt][1], axh[kt][2], axh[kt][3], l2, l3);
            }
        }

        // ---- bias + store: rows rA, rA+8; cols ch*64 + nb*8 + cq ----
#pragma unroll
        for (int nb = 0; nb < 8; ++nb) {
            int c = ch * 64 + nb * 8 + cq;
            float2 bx = *(float2*)(sBX + c);
            *(float2*)(gxo + (size_t)(b0 + rA) * C3 + c) =
                make_float2(acc[nb][0] + bx.x, acc[nb][1] + bx.y);
            *(float2*)(gxo + (size_t)(b0 + rA + 8) * C3 + c) =
                make_float2(acc[nb][2] + bx.x, acc[nb][3] + bx.y);
        }
    }
}

// ---------------------------------------------------------------------------
// Kernel B: GRU on HMMA — verbatim R8 config (best: 2.19 ms).
// 128 CTAs x 32 rows, 256 threads / 8 warps; warp w: units 16w..16w+15,
// all gates, all 32 batch. 3-term fp16 split.
// ---------------------------------------------------------------------------
#define ASTR 136
#define AMAT (HID * ASTR)
#define BSTR 40
#define SM_B0 (6 * AMAT * 2)
#define SM_B1 (SM_B0 + HID * BSTR * 2)
#define SM_TOT (SM_B1 + HID * BSTR * 2)

__global__ void __launch_bounds__(256, 1)
gru_kernel(const float* __restrict__ w_h,
           const float* __restrict__ b_h,
           const float* __restrict__ fc_w,
           const float* __restrict__ fc_b,
           float* __restrict__ out) {
    extern __shared__ char smem[];
    __half* sA = (__half*)smem;
    __half* sBhh = (__half*)(smem + SM_B0);
    __half* sBhl = (__half*)(smem + SM_B1);
    const uint32_t sb = smem_u32(smem);

    const int tid = threadIdx.x;
    const int w   = tid >> 5;
    const int L   = tid & 31;
    const int row0 = blockIdx.x * 32;
    const int uBase = 16 * w + (L >> 2);

    for (int g = 0; g < 3; ++g) {
        __half* ah = sA + (g * 2 + 0) * AMAT;
        __half* al = sA + (g * 2 + 1) * AMAT;
        const float* wg = w_h + (size_t)g * HID * HID;
        for (int idx = tid; idx < HID * HID; idx += 256) {
            int k = idx >> 7, u = idx & 127;
            float v = wg[idx];
            __half hi = __float2half_rn(v);
            __half lo = __float2half_rn(v - __half2float(hi));
            ah[u * ASTR + k] = hi;
            al[u * ASTR + k] = lo;
        }
    }
    for (int i = tid; i < HID * BSTR; i += 256) {
        sBhh[i] = __ushort_as_half(0);
        sBhl[i] = __ushort_as_half(0);
    }
    __syncthreads();

    const uint32_t lrow = (L & 7) + ((L >> 3) & 1) * 8;
    const uint32_t lcol = (L >> 4) * 8;
    uint32_t aAddr[6];
#pragma unroll
    for (int m = 0; m < 6; ++m)
        aAddr[m] = sb + (uint32_t)(m * AMAT + (16 * w + lrow) * ASTR + lcol) * 2;
    const uint32_t bAddrHH = sb + SM_B0 + (lrow * BSTR + lcol) * 2;
    const uint32_t bAddrHL = sb + SM_B1 + (lrow * BSTR + lcol) * 2;

    float bhr[2], bhz[2], bhn[2];
#pragma unroll
    for (int ui = 0; ui < 2; ++ui) {
        int u = uBase + 8 * ui;
        bhr[ui] = b_h[u];
        bhz[ui] = b_h[HID + u];
        bhn[ui] = b_h[2 * HID + u];
    }
    float hold[2][8];
#pragma unroll
    for (int ui = 0; ui < 2; ++ui)
#pragma unroll
        for (int e = 0; e < 8; ++e) hold[ui][e] = 0.0f;

    for (int t = 0; t < TT; ++t) {
        float pg[3][2][8];
        {
            const float* base = (t < 256) ? g_gx_lo : g_gx_hi;
            const float* gp = base + (size_t)(t & 255) * BB * C3;
#pragma unroll
            for (int g = 0; g < 3; ++g)
#pragma unroll
                for (int ui = 0; ui < 2; ++ui) {
                    int u = uBase + 8 * ui;
#pragma unroll
                    for (int e = 0; e < 8; ++e) {
                        int b = 8 * (e >> 1) + 2 * (L & 3) + (e & 1);
                        pg[g][ui][e] = __ldg(gp + (size_t)(row0 + b) * C3 + g * HID + u);
                    }
                }
        }

        float acc[3][4][4];
#pragma unroll
        for (int g = 0; g < 3; ++g)
#pragma unroll
            for (int nb = 0; nb < 4; ++nb)
#pragma unroll
                for (int i = 0; i < 4; ++i) acc[g][nb][i] = 0.0f;

#pragma unroll 2
        for (int kt = 0; kt < 8; ++kt) {
            uint32_t bh[4][2], bl[4][2];
#pragma unroll
            for (int nbp = 0; nbp < 2; ++nbp) {
                uint32_t r0, r1, r2, r3;
                ldsm4t(r0, r1, r2, r3, bAddrHH + kt * (16 * BSTR * 2) + nbp * 32);
                bh[2 * nbp][0] = r0; bh[2 * nbp][1] = r1;
                bh[2 * nbp + 1][0] = r2; bh[2 * nbp + 1][1] = r3;
                ldsm4t(r0, r1, r2, r3, bAddrHL + kt * (16 * BSTR * 2) + nbp * 32);
                bl[2 * nbp][0] = r0; bl[2 * nbp][1] = r1;
                bl[2 * nbp + 1][0] = r2; bl[2 * nbp + 1][1] = r3;
            }
#pragma unroll
            for (int g = 0; g < 3; ++g) {
                uint32_t ah0, ah1, ah2, ah3, al0, al1, al2, al3;
                ldsm4(ah0, ah1, ah2, ah3, aAddr[g * 2 + 0] + kt * 32);
                ldsm4(al0, al1, al2, al3, aAddr[g * 2 + 1] + kt * 32);
#pragma unroll
                for (int nb = 0; nb < 4; ++nb) {
                    mma16816(acc[g][nb], ah0, ah1, ah2, ah3, bh[nb][0], bh[nb][1]);
                    mma16816(acc[g][nb], ah0, ah1, ah2, ah3, bl[nb][0], bl[nb][1]);
                    mma16816(acc[g][nb], al0, al1, al2, al3, bh[nb][0], bh[nb][1]);
                }
            }
        }

        float hn[2][8];
#pragma unroll
        for (int ui = 0; ui < 2; ++ui)
#pragma unroll
            for (int nb = 0; nb < 4; ++nb)
#pragma unroll
                for (int q = 0; q < 2; ++q) {
                    int e = 2 * nb + q;
                    float ar = acc[0][nb][2 * ui + q] + pg[0][ui][e] + bhr[ui];
                    float az = acc[1][nb][2 * ui + q] + pg[1][ui][e] + bhz[ui];
                    float an = acc[2][nb][2 * ui + q] + bhn[ui];
                    float rr = sig1(ar);
                    float zz = sig1(az);
                    float nn = tanh1(pg[2][ui][e] + rr * an);
                    hn[ui][e] = nn + zz * (hold[ui][e] - nn);
                    hold[ui][e] = hn[ui][e];
                }

        __syncthreads();

#pragma unroll
        for (int ui = 0; ui < 2; ++ui) {
            int u = uBase + 8 * ui;
#pragma unroll
            for (int nb = 0; nb < 4; ++nb) {
                int b = 8 * nb + 2 * (L & 3);
                float v0 = hn[ui][2 * nb], v1 = hn[ui][2 * nb + 1];
                __half h0 = __float2half_rn(v0);
                __half h1 = __float2half_rn(v1);
                __half l0 = __float2half_rn(v0 - __half2float(h0));
                __half l1 = __float2half_rn(v1 - __half2float(h1));
                *(__half2*)(sBhh + u * BSTR + b) = __halves2half2(h0, h1);
                *(__half2*)(sBhl + u * BSTR + b) = __halves2half2(l0, l1);
            }
        }
        __syncthreads();
    }

    float* sH  = (float*)smem;
    float* sFW = (float*)smem + HID * 33;
#pragma unroll
    for (int ui = 0; ui < 2; ++ui) {
        int u = uBase + 8 * ui;
#pragma unroll
        for (int e = 0; e < 8; ++e) {
            int b = 8 * (e >> 1) + 2 * (L & 3) + (e & 1);
            sH[u * 33 + b] = hold[ui][e];
        }
    }
    for (int i = tid; i < HID * 10; i += 256) sFW[i] = fc_w[i];
    __syncthreads();
    for (int i = tid; i < 32 * 10; i += 256) {
        int lr = i / 10, col = i % 10;
        float s = fc_b[col];
#pragma unroll 8
        for (int uu = 0; uu < HID; ++uu)
            s += sH[uu * 33 + lr] * sFW[uu * 10 + col];
        out[(size_t)(row0 + lr) * 10 + col] = s;
    }
}

extern "C" void kernel_launch(void* const* d_in, const int* in_sizes, int n_in,
                              void* d_out, int out_size) {
    const float* x    = (const float*)d_in[0];
    const float* w_x  = (const float*)d_in[1];
    const float* b_x  = (const float*)d_in[2];
    const float* w_h  = (const float*)d_in[3];
    const float* b_h  = (const float*)d_in[4];
    const float* fc_w = (const float*)d_in[5];
    const float* fc_b = (const float*)d_in[6];
    float* out = (float*)d_out;

    cudaFuncSetAttribute(gx_kernel,  cudaFuncAttributeMaxDynamicSharedMemorySize, GSM_TOT);
    cudaFuncSetAttribute(gru_kernel, cudaFuncAttributeMaxDynamicSharedMemorySize, SM_TOT);

    gx_kernel<<<dim3(32, TT), 256, GSM_TOT>>>(x, w_x, b_x);
    gru_kernel<<<128, 256, SM_TOT>>>(w_h, b_h, fc_w, fc_b, out);
}

// round 12
// speedup vs baseline: 1.1543x; 1.0069x over previous
#include <cuda_runtime.h>
#include <cuda_fp16.h>
#include <cstdint>
#include <cstddef>

#define HID 128
#define C3  384
#define TT  512
#define BB  4096
#define INP 28

// 3.2 GB scratch: gx[t][b][c], c = g*128+u (NO bias: b_x folded into gru).
__device__ __align__(16) float g_gx_lo[(size_t)256 * BB * C3];
__device__ __align__(16) float g_gx_hi[(size_t)256 * BB * C3];

static __device__ __forceinline__ float sig1(float x) {
    float e = __expf(-x);
    return __fdividef(1.0f, 1.0f + e);
}
static __device__ __forceinline__ float tanh1(float x) {
    float e = __expf(2.0f * x);
    return 1.0f - __fdividef(2.0f, e + 1.0f);
}
static __device__ __forceinline__ uint32_t smem_u32(const void* p) {
    uint32_t a;
    asm("{ .reg .u64 t; cvta.to.shared.u64 t, %1; cvt.u32.u64 %0, t; }"
        : "=r"(a) : "l"(p));
    return a;
}
static __device__ __forceinline__ void ldsm4(uint32_t& r0, uint32_t& r1,
                                             uint32_t& r2, uint32_t& r3, uint32_t a) {
    asm volatile("ldmatrix.sync.aligned.m8n8.x4.shared.b16 {%0,%1,%2,%3}, [%4];"
                 : "=r"(r0), "=r"(r1), "=r"(r2), "=r"(r3) : "r"(a));
}
static __device__ __forceinline__ void ldsm4t(uint32_t& r0, uint32_t& r1,
                                              uint32_t& r2, uint32_t& r3, uint32_t a) {
    asm volatile("ldmatrix.sync.aligned.m8n8.x4.trans.shared.b16 {%0,%1,%2,%3}, [%4];"
                 : "=r"(r0), "=r"(r1), "=r"(r2), "=r"(r3) : "r"(a));
}
static __device__ __forceinline__ void mma16816(float* d,
        uint32_t a0, uint32_t a1, uint32_t a2, uint32_t a3,
        uint32_t b0, uint32_t b1) {
    asm volatile("mma.sync.aligned.m16n8k16.row.col.f32.f16.f16.f32 "
                 "{%0,%1,%2,%3},{%4,%5,%6,%7},{%8,%9},{%0,%1,%2,%3};"
                 : "+f"(d[0]), "+f"(d[1]), "+f"(d[2]), "+f"(d[3])
                 : "r"(a0), "r"(a1), "r"(a2), "r"(a3), "r"(b0), "r"(b1));
}

// ---------------------------------------------------------------------------
// Kernel A (HMMA): gx[t][b][c] = sum_k x[b][t][k] * w_x[k][c]  (bias folded
// into gru). CTA = (128 batch rows, t). 3-term fp16 split. Stores now staged
// through smem -> fully coalesced 256B-contiguous float4 row writes.
// ---------------------------------------------------------------------------
#define WSTR 392
#define XSTR 40
#define SSTR 68                                  // staging row stride (floats)
#define GSM_WH 0
#define GSM_WL (32 * WSTR * 2)                   // 25088
#define GSM_XH (GSM_WL + 32 * WSTR * 2)          // 50176
#define GSM_XL (GSM_XH + HID * XSTR * 2)         // 60416
#define GSM_ST (GSM_XL + HID * XSTR * 2)         // 70656
#define GSM_TOT (GSM_ST + HID * SSTR * 4)        // 105472

__global__ void __launch_bounds__(256, 2)
gx_kernel(const float* __restrict__ x,
          const float* __restrict__ w_x) {
    extern __shared__ char smem[];
    __half* sWH = (__half*)(smem + GSM_WH);
    __half* sWL = (__half*)(smem + GSM_WL);
    __half* sXH = (__half*)(smem + GSM_XH);
    __half* sXL = (__half*)(smem + GSM_XL);
    float*  sST = (float*)(smem + GSM_ST);
    const uint32_t sb = smem_u32(smem);

    const int tid = threadIdx.x;
    const int w   = tid >> 5;
    const int L   = tid & 31;
    const int b0  = blockIdx.x * 128;
    const int t   = blockIdx.y;

    // ---- w hi/lo into smem [k][c] ----
    for (int idx = tid; idx < 3 * INP * HID; idx += 256) {
        int g = idx / (INP * HID);
        int k = (idx / HID) % INP;
        int u = idx & 127;
        float v = w_x[idx];
        __half hi = __float2half_rn(v);
        __half lo = __float2half_rn(v - __half2float(hi));
        sWH[k * WSTR + g * HID + u] = hi;
        sWL[k * WSTR + g * HID + u] = lo;
    }
    for (int idx = tid; idx < 4 * C3; idx += 256) {
        int k = 28 + idx / C3, c = idx % C3;
        sWH[k * WSTR + c] = __ushort_as_half(0);
        sWL[k * WSTR + c] = __ushort_as_half(0);
    }
    // ---- x hi/lo into smem [r][k] ----
    for (int idx = tid; idx < 128 * 7; idx += 256) {
        int r = idx / 7, f = idx % 7;
        float4 v = *(const float4*)(x + ((size_t)(b0 + r) * TT + t) * INP + 4 * f);
        float vs[4] = {v.x, v.y, v.z, v.w};
#pragma unroll
        for (int j = 0; j < 4; ++j) {
            __half hi = __float2half_rn(vs[j]);
            __half lo = __float2half_rn(vs[j] - __half2float(hi));
            sXH[r * XSTR + 4 * f + j] = hi;
            sXL[r * XSTR + 4 * f + j] = lo;
        }
    }
    for (int idx = tid; idx < 128 * 4; idx += 256) {
        int r = idx >> 2, k = 28 + (idx & 3);
        sXH[r * XSTR + k] = __ushort_as_half(0);
        sXL[r * XSTR + k] = __ushort_as_half(0);
    }
    __syncthreads();

    const uint32_t lrow = (L & 7) + ((L >> 3) & 1) * 8;
    const uint32_t lcol = (L >> 4) * 8;
    const uint32_t aXH = sb + GSM_XH + (uint32_t)((16 * w + lrow) * XSTR + lcol) * 2;
    const uint32_t aXL = sb + GSM_XL + (uint32_t)((16 * w + lrow) * XSTR + lcol) * 2;
    const uint32_t bWH = sb + GSM_WH + (uint32_t)(lrow * WSTR + lcol) * 2;
    const uint32_t bWL = sb + GSM_WL + (uint32_t)(lrow * WSTR + lcol) * 2;

    // A fragments register-resident, reused across all n-chunks
    uint32_t axh[2][4], axl[2][4];
#pragma unroll
    for (int kt = 0; kt < 2; ++kt) {
        ldsm4(axh[kt][0], axh[kt][1], axh[kt][2], axh[kt][3], aXH + kt * 32);
        ldsm4(axl[kt][0], axl[kt][1], axl[kt][2], axl[kt][3], aXL + kt * 32);
    }

    float* gxo = ((t < 256) ? g_gx_lo : g_gx_hi) + (size_t)(t & 255) * BB * C3;
    const int rA = 16 * w + (L >> 2);
    const int cq = 2 * (L & 3);

#pragma unroll 1
    for (int ch = 0; ch < 6; ++ch) {
        float acc[8][4];
#pragma unroll
        for (int nb = 0; nb < 8; ++nb)
#pragma unroll
            for (int i = 0; i < 4; ++i) acc[nb][i] = 0.0f;

#pragma unroll
        for (int kt = 0; kt < 2; ++kt) {
#pragma unroll
            for (int grp = 0; grp < 4; ++grp) {
                uint32_t off = (uint32_t)(kt * 16 * WSTR + ch * 64 + grp * 16) * 2;
                uint32_t h0, h1, h2, h3, l0, l1, l2, l3;
                ldsm4t(h0, h1, h2, h3, bWH + off);
                ldsm4t(l0, l1, l2, l3, bWL + off);
                float* a0 = acc[2 * grp];
                float* a1 = acc[2 * grp + 1];
                mma16816(a0, axh[kt][0], axh[kt][1], axh[kt][2], axh[kt][3], h0, h1);
                mma16816(a0, axl[kt][0], axl[kt][1], axl[kt][2], axl[kt][3], h0, h1);
                mma16816(a0, axh[kt][0], axh[kt][1], axh[kt][2], axh[kt][3], l0, l1);
                mma16816(a1, axh[kt][0], axh[kt][1], axh[kt][2], axh[kt][3], h2, h3);
                mma16816(a1, axl[kt][0], axl[kt][1], axl[kt][2], axl[kt][3], h2, h3);
                mma16816(a1, axh[kt][0], axh[kt][1], axh[kt][2], axh[kt][3], l2, l3);
            }
        }

        // ---- stage fragments in smem, then coalesced float4 row writes ----
        __syncthreads();   // staging buffer free (prev chunk's readers done)
#pragma unroll
        for (int nb = 0; nb < 8; ++nb) {
            int c = nb * 8 + cq;
            *(float2*)(sST + rA * SSTR + c)       = make_float2(acc[nb][0], acc[nb][1]);
            *(float2*)(sST + (rA + 8) * SSTR + c) = make_float2(acc[nb][2], acc[nb][3]);
        }
        __syncthreads();
#pragma unroll
        for (int i = tid; i < 2048; i += 256) {
            int r = i >> 4, f = i & 15;
            float4 v = *(const float4*)(sST + r * SSTR + 4 * f);
            *(float4*)(gxo + (size_t)(b0 + r) * C3 + ch * 64 + 4 * f) = v;
        }
    }
}

// ---------------------------------------------------------------------------
// Kernel B: GRU on HMMA (R8 config, 8 warps) + B-fragment double buffering
// across kt + b_x folded into biases. 128 CTAs x 32 rows, 256 threads.
// ---------------------------------------------------------------------------
#define ASTR 136
#define AMAT (HID * ASTR)
#define BSTR 40
#define SM_B0 (6 * AMAT * 2)
#define SM_B1 (SM_B0 + HID * BSTR * 2)
#define SM_TOT (SM_B1 + HID * BSTR * 2)

__global__ void __launch_bounds__(256, 1)
gru_kernel(const float* __restrict__ w_h,
           const float* __restrict__ b_h,
           const float* __restrict__ b_x,
           const float* __restrict__ fc_w,
           const float* __restrict__ fc_b,
           float* __restrict__ out) {
    extern __shared__ char smem[];
    __half* sA = (__half*)smem;
    __half* sBhh = (__half*)(smem + SM_B0);
    __half* sBhl = (__half*)(smem + SM_B1);
    const uint32_t sb = smem_u32(smem);

    const int tid = threadIdx.x;
    const int w   = tid >> 5;
    const int L   = tid & 31;
    const int row0 = blockIdx.x * 32;
    const int uBase = 16 * w + (L >> 2);

    for (int g = 0; g < 3; ++g) {
        __half* ah = sA + (g * 2 + 0) * AMAT;
        __half* al = sA + (g * 2 + 1) * AMAT;
        const float* wg = w_h + (size_t)g * HID * HID;
        for (int idx = tid; idx < HID * HID; idx += 256) {
            int k = idx >> 7, u = idx & 127;
            float v = wg[idx];
            __half hi = __float2half_rn(v);
            __half lo = __float2half_rn(v - __half2float(hi));
            ah[u * ASTR + k] = hi;
            al[u * ASTR + k] = lo;
        }
    }
    for (int i = tid; i < HID * BSTR; i += 256) {
        sBhh[i] = __ushort_as_half(0);
        sBhl[i] = __ushort_as_half(0);
    }
    __syncthreads();

    const uint32_t lrow = (L & 7) + ((L >> 3) & 1) * 8;
    const uint32_t lcol = (L >> 4) * 8;
    uint32_t aAddr[6];
#pragma unroll
    for (int m = 0; m < 6; ++m)
        aAddr[m] = sb + (uint32_t)(m * AMAT + (16 * w + lrow) * ASTR + lcol) * 2;
    const uint32_t bAddrHH = sb + SM_B0 + (lrow * BSTR + lcol) * 2;
    const uint32_t bAddrHL = sb + SM_B1 + (lrow * BSTR + lcol) * 2;

    // biases with b_x folded (r,z); n keeps b_h inside, b_x outside
    float bhr[2], bhz[2], bhn[2], bxn[2];
#pragma unroll
    for (int ui = 0; ui < 2; ++ui) {
        int u = uBase + 8 * ui;
        bhr[ui] = b_h[u]           + b_x[u];
        bhz[ui] = b_h[HID + u]     + b_x[HID + u];
        bhn[ui] = b_h[2 * HID + u];
        bxn[ui] = b_x[2 * HID + u];
    }
    float hold[2][8];
#pragma unroll
    for (int ui = 0; ui < 2; ++ui)
#pragma unroll
        for (int e = 0; e < 8; ++e) hold[ui][e] = 0.0f;

    for (int t = 0; t < TT; ++t) {
        float pg[3][2][8];
        {
            const float* base = (t < 256) ? g_gx_lo : g_gx_hi;
            const float* gp = base + (size_t)(t & 255) * BB * C3;
#pragma unroll
            for (int g = 0; g < 3; ++g)
#pragma unroll
                for (int ui = 0; ui < 2; ++ui) {
                    int u = uBase + 8 * ui;
#pragma unroll
                    for (int e = 0; e < 8; ++e) {
                        int b = 8 * (e >> 1) + 2 * (L & 3) + (e & 1);
                        pg[g][ui][e] = __ldg(gp + (size_t)(row0 + b) * C3 + g * HID + u);
                    }
                }
        }

        float acc[3][4][4];
#pragma unroll
        for (int g = 0; g < 3; ++g)
#pragma unroll
            for (int nb = 0; nb < 4; ++nb)
#pragma unroll
                for (int i = 0; i < 4; ++i) acc[g][nb][i] = 0.0f;

        // B fragments double-buffered across kt
        uint32_t bfh[2][4][2], bfl[2][4][2];
#pragma unroll
        for (int nbp = 0; nbp < 2; ++nbp) {
            uint32_t r0, r1, r2, r3;
            ldsm4t(r0, r1, r2, r3, bAddrHH + nbp * 32);
            bfh[0][2 * nbp][0] = r0; bfh[0][2 * nbp][1] = r1;
            bfh[0][2 * nbp + 1][0] = r2; bfh[0][2 * nbp + 1][1] = r3;
            ldsm4t(r0, r1, r2, r3, bAddrHL + nbp * 32);
            bfl[0][2 * nbp][0] = r0; bfl[0][2 * nbp][1] = r1;
            bfl[0][2 * nbp + 1][0] = r2; bfl[0][2 * nbp + 1][1] = r3;
        }

#pragma unroll
        for (int kt = 0; kt < 8; ++kt) {
            const int cur = kt & 1, nxt = cur ^ 1;
            if (kt < 7) {
                uint32_t base = (uint32_t)((kt + 1) * 16 * BSTR * 2);
#pragma unroll
                for (int nbp = 0; nbp < 2; ++nbp) {
                    uint32_t r0, r1, r2, r3;
                    ldsm4t(r0, r1, r2, r3, bAddrHH + base + nbp * 32);
                    bfh[nxt][2 * nbp][0] = r0; bfh[nxt][2 * nbp][1] = r1;
                    bfh[nxt][2 * nbp + 1][0] = r2; bfh[nxt][2 * nbp + 1][1] = r3;
                    ldsm4t(r0, r1, r2, r3, bAddrHL + base + nbp * 32);
                    bfl[nxt][2 * nbp][0] = r0; bfl[nxt][2 * nbp][1] = r1;
                    bfl[nxt][2 * nbp + 1][0] = r2; bfl[nxt][2 * nbp + 1][1] = r3;
                }
            }
#pragma unroll
            for (int g = 0; g < 3; ++g) {
                uint32_t ah0, ah1, ah2, ah3, al0, al1, al2, al3;
                ldsm4(ah0, ah1, ah2, ah3, aAddr[g * 2 + 0] + kt * 32);
                ldsm4(al0, al1, al2, al3, aAddr[g * 2 + 1] + kt * 32);
#pragma unroll
                for (int nb = 0; nb < 4; ++nb) {
                    mma16816(acc[g][nb], ah0, ah1, ah2, ah3, bfh[cur][nb][0], bfh[cur][nb][1]);
                    mma16816(acc[g][nb], ah0, ah1, ah2, ah3, bfl[cur][nb][0], bfl[cur][nb][1]);
                    mma16816(acc[g][nb], al0, al1, al2, al3, bfh[cur][nb][0], bfh[cur][nb][1]);
                }
            }
        }

        float hn[2][8];
#pragma unroll
        for (int ui = 0; ui < 2; ++ui)
#pragma unroll
            for (int nb = 0; nb < 4; ++nb)
#pragma unroll
                for (int q = 0; q < 2; ++q) {
                    int e = 2 * nb + q;
                    float ar = acc[0][nb][2 * ui + q] + pg[0][ui][e] + bhr[ui];
                    float az = acc[1][nb][2 * ui + q] + pg[1][ui][e] + bhz[ui];
                    float an = acc[2][nb][2 * ui + q] + bhn[ui];
                    float rr = sig1(ar);
                    float zz = sig1(az);
                    float nn = tanh1(pg[2][ui][e] + bxn[ui] + rr * an);
                    hn[ui][e] = nn + zz * (hold[ui][e] - nn);
                    hold[ui][e] = hn[ui][e];
                }

        __syncthreads();

#pragma unroll
        for (int ui = 0; ui < 2; ++ui) {
            int u = uBase + 8 * ui;
#pragma unroll
            for (int nb = 0; nb < 4; ++nb) {
                int b = 8 * nb + 2 * (L & 3);
                float v0 = hn[ui][2 * nb], v1 = hn[ui][2 * nb + 1];
                __half h0 = __float2half_rn(v0);
                __half h1 = __float2half_rn(v1);
                __half l0 = __float2half_rn(v0 - __half2float(h0));
                __half l1 = __float2half_rn(v1 - __half2float(h1));
                *(__half2*)(sBhh + u * BSTR + b) = __halves2half2(h0, h1);
                *(__half2*)(sBhl + u * BSTR + b) = __halves2half2(l0, l1);
            }
        }
        __syncthreads();
    }

    float* sH  = (float*)smem;
    float* sFW = (float*)smem + HID * 33;
#pragma unroll
    for (int ui = 0; ui < 2; ++ui) {
        int u = uBase + 8 * ui;
#pragma unroll
        for (int e = 0; e < 8; ++e) {
            int b = 8 * (e >> 1) + 2 * (L & 3) + (e & 1);
            sH[u * 33 + b] = hold[ui][e];
        }
    }
    for (int i = tid; i < HID * 10; i += 256) sFW[i] = fc_w[i];
    __syncthreads();
    for (int i = tid; i < 32 * 10; i += 256) {
        int lr = i / 10, col = i % 10;
        float s = fc_b[col];
#pragma unroll 8
        for (int uu = 0; uu < HID; ++uu)
            s += sH[uu * 33 + lr] * sFW[uu * 10 + col];
        out[(size_t)(row0 + lr) * 10 + col] = s;
    }
}

extern "C" void kernel_launch(void* const* d_in, const int* in_sizes, int n_in,
                              void* d_out, int out_size) {
    const float* x    = (const float*)d_in[0];
    const float* w_x  = (const float*)d_in[1];
    const float* b_x  = (const float*)d_in[2];
    const float* w_h  = (const float*)d_in[3];
    const float* b_h  = (const float*)d_in[4];
    const float* fc_w = (const float*)d_in[5];
    const float* fc_b = (const float*)d_in[6];
    float* out = (float*)d_out;

    cudaFuncSetAttribute(gx_kernel,  cudaFuncAttributeMaxDynamicSharedMemorySize, GSM_TOT);
    cudaFuncSetAttribute(gru_kernel, cudaFuncAttributeMaxDynamicSharedMemorySize, SM_TOT);

    gx_kernel<<<dim3(32, TT), 256, GSM_TOT>>>(x, w_x);
    gru_kernel<<<128, 256, SM_TOT>>>(w_h, b_h, b_x, fc_w, fc_b, out);
}

// round 13
// speedup vs baseline: 1.2065x; 1.0452x over previous
#include <cuda_runtime.h>
#include <cuda_fp16.h>
#include <cstdint>
#include <cstddef>

#define HID 128
#define C3  384
#define TT  512
#define BB  4096
#define INP 28

// 3.2 GB scratch: gx[t][b][c], c = g*128+u (b_x folded into gru biases).
__device__ __align__(16) float g_gx_lo[(size_t)256 * BB * C3];
__device__ __align__(16) float g_gx_hi[(size_t)256 * BB * C3];

static __device__ __forceinline__ float sig1(float x) {
    float e = __expf(-x);
    return __fdividef(1.0f, 1.0f + e);
}
static __device__ __forceinline__ float tanh1(float x) {
    float e = __expf(2.0f * x);
    return 1.0f - __fdividef(2.0f, e + 1.0f);
}
static __device__ __forceinline__ uint32_t smem_u32(const void* p) {
    uint32_t a;
    asm("{ .reg .u64 t; cvta.to.shared.u64 t, %1; cvt.u32.u64 %0, t; }"
        : "=r"(a) : "l"(p));
    return a;
}
static __device__ __forceinline__ void ldsm4(uint32_t& r0, uint32_t& r1,
                                             uint32_t& r2, uint32_t& r3, uint32_t a) {
    asm volatile("ldmatrix.sync.aligned.m8n8.x4.shared.b16 {%0,%1,%2,%3}, [%4];"
                 : "=r"(r0), "=r"(r1), "=r"(r2), "=r"(r3) : "r"(a));
}
static __device__ __forceinline__ void ldsm4t(uint32_t& r0, uint32_t& r1,
                                              uint32_t& r2, uint32_t& r3, uint32_t a) {
    asm volatile("ldmatrix.sync.aligned.m8n8.x4.trans.shared.b16 {%0,%1,%2,%3}, [%4];"
                 : "=r"(r0), "=r"(r1), "=r"(r2), "=r"(r3) : "r"(a));
}
static __device__ __forceinline__ void mma16816(float* d,
        uint32_t a0, uint32_t a1, uint32_t a2, uint32_t a3,
        uint32_t b0, uint32_t b1) {
    asm volatile("mma.sync.aligned.m16n8k16.row.col.f32.f16.f16.f32 "
                 "{%0,%1,%2,%3},{%4,%5,%6,%7},{%8,%9},{%0,%1,%2,%3};"
                 : "+f"(d[0]), "+f"(d[1]), "+f"(d[2]), "+f"(d[3])
                 : "r"(a0), "r"(a1), "r"(a2), "r"(a3), "r"(b0), "r"(b1));
}

// ---------------------------------------------------------------------------
// Kernel A (HMMA): gx[t][b][c] = sum_k x[b][t][k] * w_x[k][c]  (no bias).
// R11 config: direct float2 fragment stores (full 32B sectors), no staging.
// ---------------------------------------------------------------------------
#define WSTR 392
#define XSTR 40
#define GSM_WH 0
#define GSM_WL (32 * WSTR * 2)
#define GSM_XH (GSM_WL + 32 * WSTR * 2)
#define GSM_XL (GSM_XH + HID * XSTR * 2)
#define GSM_TOT (GSM_XL + HID * XSTR * 2)        // 70656

__global__ void __launch_bounds__(256, 2)
gx_kernel(const float* __restrict__ x,
          const float* __restrict__ w_x) {
    extern __shared__ char smem[];
    __half* sWH = (__half*)(smem + GSM_WH);
    __half* sWL = (__half*)(smem + GSM_WL);
    __half* sXH = (__half*)(smem + GSM_XH);
    __half* sXL = (__half*)(smem + GSM_XL);
    const uint32_t sb = smem_u32(smem);

    const int tid = threadIdx.x;
    const int w   = tid >> 5;
    const int L   = tid & 31;
    const int b0  = blockIdx.x * 128;
    const int t   = blockIdx.y;

    for (int idx = tid; idx < 3 * INP * HID; idx += 256) {
        int g = idx / (INP * HID);
        int k = (idx / HID) % INP;
        int u = idx & 127;
        float v = w_x[idx];
        __half hi = __float2half_rn(v);
        __half lo = __float2half_rn(v - __half2float(hi));
        sWH[k * WSTR + g * HID + u] = hi;
        sWL[k * WSTR + g * HID + u] = lo;
    }
    for (int idx = tid; idx < 4 * C3; idx += 256) {
        int k = 28 + idx / C3, c = idx % C3;
        sWH[k * WSTR + c] = __ushort_as_half(0);
        sWL[k * WSTR + c] = __ushort_as_half(0);
    }
    for (int idx = tid; idx < 128 * 7; idx += 256) {
        int r = idx / 7, f = idx % 7;
        float4 v = *(const float4*)(x + ((size_t)(b0 + r) * TT + t) * INP + 4 * f);
        float vs[4] = {v.x, v.y, v.z, v.w};
#pragma unroll
        for (int j = 0; j < 4; ++j) {
            __half hi = __float2half_rn(vs[j]);
            __half lo = __float2half_rn(vs[j] - __half2float(hi));
            sXH[r * XSTR + 4 * f + j] = hi;
            sXL[r * XSTR + 4 * f + j] = lo;
        }
    }
    for (int idx = tid; idx < 128 * 4; idx += 256) {
        int r = idx >> 2, k = 28 + (idx & 3);
        sXH[r * XSTR + k] = __ushort_as_half(0);
        sXL[r * XSTR + k] = __ushort_as_half(0);
    }
    __syncthreads();

    const uint32_t lrow = (L & 7) + ((L >> 3) & 1) * 8;
    const uint32_t lcol = (L >> 4) * 8;
    const uint32_t aXH = sb + GSM_XH + (uint32_t)((16 * w + lrow) * XSTR + lcol) * 2;
    const uint32_t aXL = sb + GSM_XL + (uint32_t)((16 * w + lrow) * XSTR + lcol) * 2;
    const uint32_t bWH = sb + GSM_WH + (uint32_t)(lrow * WSTR + lcol) * 2;
    const uint32_t bWL = sb + GSM_WL + (uint32_t)(lrow * WSTR + lcol) * 2;

    uint32_t axh[2][4], axl[2][4];
#pragma unroll
    for (int kt = 0; kt < 2; ++kt) {
        ldsm4(axh[kt][0], axh[kt][1], axh[kt][2], axh[kt][3], aXH + kt * 32);
        ldsm4(axl[kt][0], axl[kt][1], axl[kt][2], axl[kt][3], aXL + kt * 32);
    }

    float* gxo = ((t < 256) ? g_gx_lo : g_gx_hi) + (size_t)(t & 255) * BB * C3;
    const int rA = 16 * w + (L >> 2);
    const int cq = 2 * (L & 3);

#pragma unroll 1
    for (int ch = 0; ch < 6; ++ch) {
        float acc[8][4];
#pragma unroll
        for (int nb = 0; nb < 8; ++nb)
#pragma unroll
            for (int i = 0; i < 4; ++i) acc[nb][i] = 0.0f;

#pragma unroll
        for (int kt = 0; kt < 2; ++kt) {
#pragma unroll
            for (int grp = 0; grp < 4; ++grp) {
                uint32_t off = (uint32_t)(kt * 16 * WSTR + ch * 64 + grp * 16) * 2;
                uint32_t h0, h1, h2, h3, l0, l1, l2, l3;
                ldsm4t(h0, h1, h2, h3, bWH + off);
                ldsm4t(l0, l1, l2, l3, bWL + off);
                float* a0 = acc[2 * grp];
                float* a1 = acc[2 * grp + 1];
                mma16816(a0, axh[kt][0], axh[kt][1], axh[kt][2], axh[kt][3], h0, h1);
                mma16816(a0, axl[kt][0], axl[kt][1], axl[kt][2], axl[kt][3], h0, h1);
                mma16816(a0, axh[kt][0], axh[kt][1], axh[kt][2], axh[kt][3], l0, l1);
                mma16816(a1, axh[kt][0], axh[kt][1], axh[kt][2], axh[kt][3], h2, h3);
                mma16816(a1, axl[kt][0], axl[kt][1], axl[kt][2], axl[kt][3], h2, h3);
                mma16816(a1, axh[kt][0], axh[kt][1], axh[kt][2], axh[kt][3], l2, l3);
            }
        }

#pragma unroll
        for (int nb = 0; nb < 8; ++nb) {
            int c = ch * 64 + nb * 8 + cq;
            *(float2*)(gxo + (size_t)(b0 + rA) * C3 + c) =
                make_float2(acc[nb][0], acc[nb][1]);
            *(float2*)(gxo + (size_t)(b0 + rA + 8) * C3 + c) =
                make_float2(acc[nb][2], acc[nb][3]);
        }
    }
}

// ---------------------------------------------------------------------------
// Kernel B: GRU on HMMA, batch-split software pipeline. Two independent
// 16-batch halves per CTA; schedule mma0(t) / gates1(t-1) / bar / mma1(t) /
// gates0(t) / bar so the MUFU gate burst of one half overlaps tensor work
// of the other. 128 CTAs x 32 rows, 256 threads / 8 warps.
// ---------------------------------------------------------------------------
#define ASTR 136
#define AMAT (HID * ASTR)
#define BSTR 40
#define SM_B0 (6 * AMAT * 2)
#define SM_B1 (SM_B0 + HID * BSTR * 2)
#define SM_TOT (SM_B1 + HID * BSTR * 2)

__global__ void __launch_bounds__(256, 1)
gru_kernel(const float* __restrict__ w_h,
           const float* __restrict__ b_h,
           const float* __restrict__ b_x,
           const float* __restrict__ fc_w,
           const float* __restrict__ fc_b,
           float* __restrict__ out) {
    extern __shared__ char smem[];
    __half* sA = (__half*)smem;
    __half* sBhh = (__half*)(smem + SM_B0);
    __half* sBhl = (__half*)(smem + SM_B1);
    const uint32_t sb = smem_u32(smem);

    const int tid = threadIdx.x;
    const int w   = tid >> 5;
    const int L   = tid & 31;
    const int row0 = blockIdx.x * 32;
    const int uBase = 16 * w + (L >> 2);

    for (int g = 0; g < 3; ++g) {
        __half* ah = sA + (g * 2 + 0) * AMAT;
        __half* al = sA + (g * 2 + 1) * AMAT;
        const float* wg = w_h + (size_t)g * HID * HID;
        for (int idx = tid; idx < HID * HID; idx += 256) {
            int k = idx >> 7, u = idx & 127;
            float v = wg[idx];
            __half hi = __float2half_rn(v);
            __half lo = __float2half_rn(v - __half2float(hi));
            ah[u * ASTR + k] = hi;
            al[u * ASTR + k] = lo;
        }
    }
    for (int i = tid; i < HID * BSTR; i += 256) {
        sBhh[i] = __ushort_as_half(0);
        sBhl[i] = __ushort_as_half(0);
    }
    __syncthreads();

    const uint32_t lrow = (L & 7) + ((L >> 3) & 1) * 8;
    const uint32_t lcol = (L >> 4) * 8;
    uint32_t aAddr[6];
#pragma unroll
    for (int m = 0; m < 6; ++m)
        aAddr[m] = sb + (uint32_t)(m * AMAT + (16 * w + lrow) * ASTR + lcol) * 2;
    const uint32_t bAddrHH = sb + SM_B0 + (lrow * BSTR + lcol) * 2;
    const uint32_t bAddrHL = sb + SM_B1 + (lrow * BSTR + lcol) * 2;

    float bhr[2], bhz[2], bhn[2], bxn[2];
#pragma unroll
    for (int ui = 0; ui < 2; ++ui) {
        int u = uBase + 8 * ui;
        bhr[ui] = b_h[u]           + b_x[u];
        bhz[ui] = b_h[HID + u]     + b_x[HID + u];
        bhn[ui] = b_h[2 * HID + u];
        bxn[ui] = b_x[2 * HID + u];
    }

    float hold0[2][4], hold1[2][4];
#pragma unroll
    for (int ui = 0; ui < 2; ++ui)
#pragma unroll
        for (int e = 0; e < 4; ++e) { hold0[ui][e] = 0.0f; hold1[ui][e] = 0.0f; }

    float acc0[3][2][4], acc1[3][2][4];
    float pg0[3][2][4], pg1[3][2][4];

    // ---- helpers as macros over locals ----
#define LOAD_PG(PG, T, HF) do {                                               \
    const float* _b = ((T) < 256) ? g_gx_lo : g_gx_hi;                        \
    const float* _gp = _b + (size_t)((T) & 255) * BB * C3;                    \
    _Pragma("unroll")                                                         \
    for (int g = 0; g < 3; ++g)                                               \
        _Pragma("unroll")                                                     \
        for (int ui = 0; ui < 2; ++ui) {                                      \
            int u = uBase + 8 * ui;                                           \
            _Pragma("unroll")                                                 \
            for (int e = 0; e < 4; ++e) {                                     \
                int b = 16 * (HF) + 8 * (e >> 1) + 2 * (L & 3) + (e & 1);     \
                PG[g][ui][e] = __ldg(_gp + (size_t)(row0 + b) * C3 + g * HID + u); \
            }                                                                 \
        }                                                                     \
} while (0)

#define MMA_PHASE(ACC, HF) do {                                               \
    _Pragma("unroll")                                                         \
    for (int g = 0; g < 3; ++g)                                               \
        _Pragma("unroll")                                                     \
        for (int nb = 0; nb < 2; ++nb)                                        \
            _Pragma("unroll")                                                 \
            for (int i = 0; i < 4; ++i) ACC[g][nb][i] = 0.0f;                 \
    _Pragma("unroll")                                                         \
    for (int kt = 0; kt < 8; ++kt) {                                          \
        uint32_t bh0, bh1, bh2, bh3, bl0, bl1, bl2, bl3;                      \
        uint32_t boff = (uint32_t)(kt * 16 * BSTR * 2) + (HF) * 32;           \
        ldsm4t(bh0, bh1, bh2, bh3, bAddrHH + boff);                           \
        ldsm4t(bl0, bl1, bl2, bl3, bAddrHL + boff);                           \
        _Pragma("unroll")                                                     \
        for (int g = 0; g < 3; ++g) {                                         \
            uint32_t ah0, ah1, ah2, ah3, al0, al1, al2, al3;                  \
            ldsm4(ah0, ah1, ah2, ah3, aAddr[g * 2 + 0] + kt * 32);            \
            ldsm4(al0, al1, al2, al3, aAddr[g * 2 + 1] + kt * 32);            \
            mma16816(ACC[g][0], ah0, ah1, ah2, ah3, bh0, bh1);                \
            mma16816(ACC[g][0], ah0, ah1, ah2, ah3, bl0, bl1);                \
            mma16816(ACC[g][0], al0, al1, al2, al3, bh0, bh1);                \
            mma16816(ACC[g][1], ah0, ah1, ah2, ah3, bh2, bh3);                \
            mma16816(ACC[g][1], ah0, ah1, ah2, ah3, bl2, bl3);                \
            mma16816(ACC[g][1], al0, al1, al2, al3, bh2, bh3);                \
        }                                                                     \
    }                                                                         \
} while (0)

#define GATES_PHASE(ACC, PG, HOLD, HF, WRITE_B) do {                          \
    _Pragma("unroll")                                                         \
    for (int ui = 0; ui < 2; ++ui) {                                          \
        int u = uBase + 8 * ui;                                               \
        _Pragma("unroll")                                                     \
        for (int nb = 0; nb < 2; ++nb) {                                      \
            float hv[2];                                                      \
            _Pragma("unroll")                                                 \
            for (int q = 0; q < 2; ++q) {                                     \
                int e = 2 * nb + q;                                           \
                float ar = ACC[0][nb][2 * ui + q] + PG[0][ui][e] + bhr[ui];   \
                float az = ACC[1][nb][2 * ui + q] + PG[1][ui][e] + bhz[ui];   \
                float an = ACC[2][nb][2 * ui + q] + bhn[ui];                  \
                float rr = sig1(ar);                                          \
                float zz = sig1(az);                                          \
                float nn = tanh1(PG[2][ui][e] + bxn[ui] + rr * an);           \
                float h  = nn + zz * (HOLD[ui][e] - nn);                      \
                HOLD[ui][e] = h;                                              \
                hv[q] = h;                                                    \
            }                                                                 \
            if (WRITE_B) {                                                    \
                int b = 16 * (HF) + 8 * nb + 2 * (L & 3);                     \
                __half h0 = __float2half_rn(hv[0]);                           \
                __half h1 = __float2half_rn(hv[1]);                           \
                __half l0 = __float2half_rn(hv[0] - __half2float(h0));        \
                __half l1 = __float2half_rn(hv[1] - __half2float(h1));        \
                *(__half2*)(sBhh + u * BSTR + b) = __halves2half2(h0, h1);    \
                *(__half2*)(sBhl + u * BSTR + b) = __halves2half2(l0, l1);    \
            }                                                                 \
        }                                                                     \
    }                                                                         \
} while (0)

    LOAD_PG(pg0, 0, 0);

    for (int t = 0; t < TT; ++t) {
        MMA_PHASE(acc0, 0);                    // reads B0(t)
        if (t > 0) GATES_PHASE(acc1, pg1, hold1, 1, 1);   // writes B1(t)
        LOAD_PG(pg1, t, 1);
        __syncthreads();                       // B1(t) visible; B0(t) reads done
        MMA_PHASE(acc1, 1);                    // reads B1(t)
        GATES_PHASE(acc0, pg0, hold0, 0, 1);   // writes B0(t+1)
        if (t + 1 < TT) LOAD_PG(pg0, t + 1, 0);
        __syncthreads();                       // B0(t+1) visible; B1(t) reads done
    }
    GATES_PHASE(acc1, pg1, hold1, 1, 0);       // final half-1 state (no B write)

    // ---- FC epilogue ----
    float* sH  = (float*)smem;              // [128][33]
    float* sFW = (float*)smem + HID * 33;
#pragma unroll
    for (int ui = 0; ui < 2; ++ui) {
        int u = uBase + 8 * ui;
#pragma unroll
        for (int e = 0; e < 4; ++e) {
            int bq = 8 * (e >> 1) + 2 * (L & 3) + (e & 1);
            sH[u * 33 + bq]      = hold0[ui][e];
            sH[u * 33 + 16 + bq] = hold1[ui][e];
        }
    }
    for (int i = tid; i < HID * 10; i += 256) sFW[i] = fc_w[i];
    __syncthreads();
    for (int i = tid; i < 32 * 10; i += 256) {
        int lr = i / 10, col = i % 10;
        float s = fc_b[col];
#pragma unroll 8
        for (int uu = 0; uu < HID; ++uu)
            s += sH[uu * 33 + lr] * sFW[uu * 10 + col];
        out[(size_t)(row0 + lr) * 10 + col] = s;
    }
#undef LOAD_PG
#undef MMA_PHASE
#undef GATES_PHASE
}

extern "C" void kernel_launch(void* const* d_in, const int* in_sizes, int n_in,
                              void* d_out, int out_size) {
    const float* x    = (const float*)d_in[0];
    const float* w_x  = (const float*)d_in[1];
    const float* b_x  = (const float*)d_in[2];
    const float* w_h  = (const float*)d_in[3];
    const float* b_h  = (const float*)d_in[4];
    const float* fc_w = (const float*)d_in[5];
    const float* fc_b = (const float*)d_in[6];
    float* out = (float*)d_out;

    cudaFuncSetAttribute(gx_kernel,  cudaFuncAttributeMaxDynamicSharedMemorySize, GSM_TOT);
    cudaFuncSetAttribute(gru_kernel, cudaFuncAttributeMaxDynamicSharedMemorySize, SM_TOT);

    gx_kernel<<<dim3(32, TT), 256, GSM_TOT>>>(x, w_x);
    gru_kernel<<<128, 256, SM_TOT>>>(w_h, b_h, b_x, fc_w, fc_b, out);
}

// round 14
// speedup vs baseline: 1.4622x; 1.2120x over previous
#include <cuda_runtime.h>
#include <cuda_fp16.h>
#include <cstdint>
#include <cstddef>

#define HID 128
#define C3  384
#define TT  512
#define BB  4096
#define INP 28

// 3.2 GB scratch: gx[t][b][c], c = g*128+u (b_x folded into gru biases).
__device__ __align__(16) float g_gx_lo[(size_t)256 * BB * C3];
__device__ __align__(16) float g_gx_hi[(size_t)256 * BB * C3];

static __device__ __forceinline__ float sig1(float x) {
    float e = __expf(-x);
    return __fdividef(1.0f, 1.0f + e);
}
static __device__ __forceinline__ float tanh1(float x) {
    float e = __expf(2.0f * x);
    return 1.0f - __fdividef(2.0f, e + 1.0f);
}
static __device__ __forceinline__ uint32_t smem_u32(const void* p) {
    uint32_t a;
    asm("{ .reg .u64 t; cvta.to.shared.u64 t, %1; cvt.u32.u64 %0, t; }"
        : "=r"(a) : "l"(p));
    return a;
}
static __device__ __forceinline__ void ldsm4(uint32_t& r0, uint32_t& r1,
                                             uint32_t& r2, uint32_t& r3, uint32_t a) {
    asm volatile("ldmatrix.sync.aligned.m8n8.x4.shared.b16 {%0,%1,%2,%3}, [%4];"
                 : "=r"(r0), "=r"(r1), "=r"(r2), "=r"(r3) : "r"(a));
}
static __device__ __forceinline__ void ldsm4t(uint32_t& r0, uint32_t& r1,
                                              uint32_t& r2, uint32_t& r3, uint32_t a) {
    asm volatile("ldmatrix.sync.aligned.m8n8.x4.trans.shared.b16 {%0,%1,%2,%3}, [%4];"
                 : "=r"(r0), "=r"(r1), "=r"(r2), "=r"(r3) : "r"(a));
}
static __device__ __forceinline__ void mma16816(float* d,
        uint32_t a0, uint32_t a1, uint32_t a2, uint32_t a3,
        uint32_t b0, uint32_t b1) {
    asm volatile("mma.sync.aligned.m16n8k16.row.col.f32.f16.f16.f32 "
                 "{%0,%1,%2,%3},{%4,%5,%6,%7},{%8,%9},{%0,%1,%2,%3};"
                 : "+f"(d[0]), "+f"(d[1]), "+f"(d[2]), "+f"(d[3])
                 : "r"(a0), "r"(a1), "r"(a2), "r"(a3), "r"(b0), "r"(b1));
}

// ---------------------------------------------------------------------------
// Kernel A (HMMA): gx[t][b][c] = sum_k x[b][t][k] * w_x[k][c]  (no bias).
// 2-term split: xh*wh + xl*wh (w quantization = fixed 2^-11 perturbation).
// ---------------------------------------------------------------------------
#define WSTR 392
#define XSTR 40
#define GSM_WH 0
#define GSM_XH (32 * WSTR * 2)                  // 25088
#define GSM_XL (GSM_XH + HID * XSTR * 2)        // 35328
#define GSM_TOT (GSM_XL + HID * XSTR * 2)       // 45568

__global__ void __launch_bounds__(256, 2)
gx_kernel(const float* __restrict__ x,
          const float* __restrict__ w_x) {
    extern __shared__ char smem[];
    __half* sWH = (__half*)(smem + GSM_WH);
    __half* sXH = (__half*)(smem + GSM_XH);
    __half* sXL = (__half*)(smem + GSM_XL);
    const uint32_t sb = smem_u32(smem);

    const int tid = threadIdx.x;
    const int w   = tid >> 5;
    const int L   = tid & 31;
    const int b0  = blockIdx.x * 128;
    const int t   = blockIdx.y;

    for (int idx = tid; idx < 3 * INP * HID; idx += 256) {
        int g = idx / (INP * HID);
        int k = (idx / HID) % INP;
        int u = idx & 127;
        sWH[k * WSTR + g * HID + u] = __float2half_rn(w_x[idx]);
    }
    for (int idx = tid; idx < 4 * C3; idx += 256) {
        int k = 28 + idx / C3, c = idx % C3;
        sWH[k * WSTR + c] = __ushort_as_half(0);
    }
    for (int idx = tid; idx < 128 * 7; idx += 256) {
        int r = idx / 7, f = idx % 7;
        float4 v = *(const float4*)(x + ((size_t)(b0 + r) * TT + t) * INP + 4 * f);
        float vs[4] = {v.x, v.y, v.z, v.w};
#pragma unroll
        for (int j = 0; j < 4; ++j) {
            __half hi = __float2half_rn(vs[j]);
            __half lo = __float2half_rn(vs[j] - __half2float(hi));
            sXH[r * XSTR + 4 * f + j] = hi;
            sXL[r * XSTR + 4 * f + j] = lo;
        }
    }
    for (int idx = tid; idx < 128 * 4; idx += 256) {
        int r = idx >> 2, k = 28 + (idx & 3);
        sXH[r * XSTR + k] = __ushort_as_half(0);
        sXL[r * XSTR + k] = __ushort_as_half(0);
    }
    __syncthreads();

    const uint32_t lrow = (L & 7) + ((L >> 3) & 1) * 8;
    const uint32_t lcol = (L >> 4) * 8;
    const uint32_t aXH = sb + GSM_XH + (uint32_t)((16 * w + lrow) * XSTR + lcol) * 2;
    const uint32_t aXL = sb + GSM_XL + (uint32_t)((16 * w + lrow) * XSTR + lcol) * 2;
    const uint32_t bWH = sb + GSM_WH + (uint32_t)(lrow * WSTR + lcol) * 2;

    uint32_t axh[2][4], axl[2][4];
#pragma unroll
    for (int kt = 0; kt < 2; ++kt) {
        ldsm4(axh[kt][0], axh[kt][1], axh[kt][2], axh[kt][3], aXH + kt * 32);
        ldsm4(axl[kt][0], axl[kt][1], axl[kt][2], axl[kt][3], aXL + kt * 32);
    }

    float* gxo = ((t < 256) ? g_gx_lo : g_gx_hi) + (size_t)(t & 255) * BB * C3;
    const int rA = 16 * w + (L >> 2);
    const int cq = 2 * (L & 3);

#pragma unroll 1
    for (int ch = 0; ch < 6; ++ch) {
        float acc[8][4];
#pragma unroll
        for (int nb = 0; nb < 8; ++nb)
#pragma unroll
            for (int i = 0; i < 4; ++i) acc[nb][i] = 0.0f;

#pragma unroll
        for (int kt = 0; kt < 2; ++kt) {
#pragma unroll
            for (int grp = 0; grp < 4; ++grp) {
                uint32_t off = (uint32_t)(kt * 16 * WSTR + ch * 64 + grp * 16) * 2;
                uint32_t h0, h1, h2, h3;
                ldsm4t(h0, h1, h2, h3, bWH + off);
                float* a0 = acc[2 * grp];
                float* a1 = acc[2 * grp + 1];
                mma16816(a0, axh[kt][0], axh[kt][1], axh[kt][2], axh[kt][3], h0, h1);
                mma16816(a0, axl[kt][0], axl[kt][1], axl[kt][2], axl[kt][3], h0, h1);
                mma16816(a1, axh[kt][0], axh[kt][1], axh[kt][2], axh[kt][3], h2, h3);
                mma16816(a1, axl[kt][0], axl[kt][1], axl[kt][2], axl[kt][3], h2, h3);
            }
        }

#pragma unroll
        for (int nb = 0; nb < 8; ++nb) {
            int c = ch * 64 + nb * 8 + cq;
            *(float2*)(gxo + (size_t)(b0 + rA) * C3 + c) =
                make_float2(acc[nb][0], acc[nb][1]);
            *(float2*)(gxo + (size_t)(b0 + rA + 8) * C3 + c) =
                make_float2(acc[nb][2], acc[nb][3]);
        }
    }
}

// ---------------------------------------------------------------------------
// Kernel B: GRU on HMMA, 2-term split (wh*hh + wh*hl), batch-split software
// pipeline (mma0 / gates1 / bar / mma1 / gates0 / bar). A = 3 fp16 matrices
// (102KB). 128 CTAs x 32 rows, 256 threads / 8 warps.
// ---------------------------------------------------------------------------
#define ASTR 136
#define AMAT (HID * ASTR)
#define BSTR 40
#define SM_B0 (3 * AMAT * 2)                    // 104448
#define SM_B1 (SM_B0 + HID * BSTR * 2)          // 114688
#define SM_TOT (SM_B1 + HID * BSTR * 2)         // 124928

__global__ void __launch_bounds__(256, 1)
gru_kernel(const float* __restrict__ w_h,
           const float* __restrict__ b_h,
           const float* __restrict__ b_x,
           const float* __restrict__ fc_w,
           const float* __restrict__ fc_b,
           float* __restrict__ out) {
    extern __shared__ char smem[];
    __half* sA = (__half*)smem;
    __half* sBhh = (__half*)(smem + SM_B0);
    __half* sBhl = (__half*)(smem + SM_B1);
    const uint32_t sb = smem_u32(smem);

    const int tid = threadIdx.x;
    const int w   = tid >> 5;
    const int L   = tid & 31;
    const int row0 = blockIdx.x * 32;
    const int uBase = 16 * w + (L >> 2);

    for (int g = 0; g < 3; ++g) {
        __half* ah = sA + g * AMAT;
        const float* wg = w_h + (size_t)g * HID * HID;
        for (int idx = tid; idx < HID * HID; idx += 256) {
            int k = idx >> 7, u = idx & 127;
            ah[u * ASTR + k] = __float2half_rn(wg[idx]);
        }
    }
    for (int i = tid; i < HID * BSTR; i += 256) {
        sBhh[i] = __ushort_as_half(0);
        sBhl[i] = __ushort_as_half(0);
    }
    __syncthreads();

    const uint32_t lrow = (L & 7) + ((L >> 3) & 1) * 8;
    const uint32_t lcol = (L >> 4) * 8;
    uint32_t aAddr[3];
#pragma unroll
    for (int m = 0; m < 3; ++m)
        aAddr[m] = sb + (uint32_t)(m * AMAT + (16 * w + lrow) * ASTR + lcol) * 2;
    const uint32_t bAddrHH = sb + SM_B0 + (lrow * BSTR + lcol) * 2;
    const uint32_t bAddrHL = sb + SM_B1 + (lrow * BSTR + lcol) * 2;

    float bhr[2], bhz[2], bhn[2], bxn[2];
#pragma unroll
    for (int ui = 0; ui < 2; ++ui) {
        int u = uBase + 8 * ui;
        bhr[ui] = b_h[u]           + b_x[u];
        bhz[ui] = b_h[HID + u]     + b_x[HID + u];
        bhn[ui] = b_h[2 * HID + u];
        bxn[ui] = b_x[2 * HID + u];
    }

    float hold0[2][4], hold1[2][4];
#pragma unroll
    for (int ui = 0; ui < 2; ++ui)
#pragma unroll
        for (int e = 0; e < 4; ++e) { hold0[ui][e] = 0.0f; hold1[ui][e] = 0.0f; }

    float acc0[3][2][4], acc1[3][2][4];
    float pg0[3][2][4], pg1[3][2][4];

#define LOAD_PG(PG, T, HF) do {                                               \
    const float* _b = ((T) < 256) ? g_gx_lo : g_gx_hi;                        \
    const float* _gp = _b + (size_t)((T) & 255) * BB * C3;                    \
    _Pragma("unroll")                                                         \
    for (int g = 0; g < 3; ++g)                                               \
        _Pragma("unroll")                                                     \
        for (int ui = 0; ui < 2; ++ui) {                                      \
            int u = uBase + 8 * ui;                                           \
            _Pragma("unroll")                                                 \
            for (int e = 0; e < 4; ++e) {                                     \
                int b = 16 * (HF) + 8 * (e >> 1) + 2 * (L & 3) + (e & 1);     \
                PG[g][ui][e] = __ldg(_gp + (size_t)(row0 + b) * C3 + g * HID + u); \
            }                                                                 \
        }                                                                     \
} while (0)

#define MMA_PHASE(ACC, HF) do {                                               \
    _Pragma("unroll")                                                         \
    for (int g = 0; g < 3; ++g)                                               \
        _Pragma("unroll")                                                     \
        for (int nb = 0; nb < 2; ++nb)                                        \
            _Pragma("unroll")                                                 \
            for (int i = 0; i < 4; ++i) ACC[g][nb][i] = 0.0f;                 \
    _Pragma("unroll")                                                         \
    for (int kt = 0; kt < 8; ++kt) {                                          \
        uint32_t bh0, bh1, bh2, bh3, bl0, bl1, bl2, bl3;                      \
        uint32_t boff = (uint32_t)(kt * 16 * BSTR * 2) + (HF) * 32;           \
        ldsm4t(bh0, bh1, bh2, bh3, bAddrHH + boff);                           \
        ldsm4t(bl0, bl1, bl2, bl3, bAddrHL + boff);                           \
        _Pragma("unroll")                                                     \
        for (int g = 0; g < 3; ++g) {                                         \
            uint32_t ah0, ah1, ah2, ah3;                                      \
            ldsm4(ah0, ah1, ah2, ah3, aAddr[g] + kt * 32);                    \
            mma16816(ACC[g][0], ah0, ah1, ah2, ah3, bh0, bh1);                \
            mma16816(ACC[g][0], ah0, ah1, ah2, ah3, bl0, bl1);                \
            mma16816(ACC[g][1], ah0, ah1, ah2, ah3, bh2, bh3);                \
            mma16816(ACC[g][1], ah0, ah1, ah2, ah3, bl2, bl3);                \
        }                                                                     \
    }                                                                         \
} while (0)

#define GATES_PHASE(ACC, PG, HOLD, HF, WRITE_B) do {                          \
    _Pragma("unroll")                                                         \
    for (int ui = 0; ui < 2; ++ui) {                                          \
        int u = uBase + 8 * ui;                                               \
        _Pragma("unroll")                                                     \
        for (int nb = 0; nb < 2; ++nb) {                                      \
            float hv[2];                                                      \
            _Pragma("unroll")                                                 \
            for (int q = 0; q < 2; ++q) {                                     \
                int e = 2 * nb + q;                                           \
                float ar = ACC[0][nb][2 * ui + q] + PG[0][ui][e] + bhr[ui];   \
                float az = ACC[1][nb][2 * ui + q] + PG[1][ui][e] + bhz[ui];   \
                float an = ACC[2][nb][2 * ui + q] + bhn[ui];                  \
                float rr = sig1(ar);                                          \
                float zz = sig1(az);                                          \
                float nn = tanh1(PG[2][ui][e] + bxn[ui] + rr * an);           \
                float h  = nn + zz * (HOLD[ui][e] - nn);                      \
                HOLD[ui][e] = h;                                              \
                hv[q] = h;                                                    \
            }                                                                 \
            if (WRITE_B) {                                                    \
                int b = 16 * (HF) + 8 * nb + 2 * (L & 3);                     \
                __half h0 = __float2half_rn(hv[0]);                           \
                __half h1 = __float2half_rn(hv[1]);                           \
                __half l0 = __float2half_rn(hv[0] - __half2float(h0));        \
                __half l1 = __float2half_rn(hv[1] - __half2float(h1));        \
                *(__half2*)(sBhh + u * BSTR + b) = __halves2half2(h0, h1);    \
                *(__half2*)(sBhl + u * BSTR + b) = __halves2half2(l0, l1);    \
            }                                                                 \
        }                                                                     \
    }                                                                         \
} while (0)

    LOAD_PG(pg0, 0, 0);

    for (int t = 0; t < TT; ++t) {
        MMA_PHASE(acc0, 0);                    // reads B0(t)
        if (t > 0) GATES_PHASE(acc1, pg1, hold1, 1, 1);   // writes B1(t)
        LOAD_PG(pg1, t, 1);
        __syncthreads();
        MMA_PHASE(acc1, 1);                    // reads B1(t)
        GATES_PHASE(acc0, pg0, hold0, 0, 1);   // writes B0(t+1)
        if (t + 1 < TT) LOAD_PG(pg0, t + 1, 0);
        __syncthreads();
    }
    GATES_PHASE(acc1, pg1, hold1, 1, 0);

    // ---- FC epilogue ----
    float* sH  = (float*)smem;
    float* sFW = (float*)smem + HID * 33;
#pragma unroll
    for (int ui = 0; ui < 2; ++ui) {
        int u = uBase + 8 * ui;
#pragma unroll
        for (int e = 0; e < 4; ++e) {
            int bq = 8 * (e >> 1) + 2 * (L & 3) + (e & 1);
            sH[u * 33 + bq]      = hold0[ui][e];
            sH[u * 33 + 16 + bq] = hold1[ui][e];
        }
    }
    for (int i = tid; i < HID * 10; i += 256) sFW[i] = fc_w[i];
    __syncthreads();
    for (int i = tid; i < 32 * 10; i += 256) {
        int lr = i / 10, col = i % 10;
        float s = fc_b[col];
#pragma unroll 8
        for (int uu = 0; uu < HID; ++uu)
            s += sH[uu * 33 + lr] * sFW[uu * 10 + col];
        out[(size_t)(row0 + lr) * 10 + col] = s;
    }
#undef LOAD_PG
#undef MMA_PHASE
#undef GATES_PHASE
}

extern "C" void kernel_launch(void* const* d_in, const int* in_sizes, int n_in,
                              void* d_out, int out_size) {
    const float* x    = (const float*)d_in[0];
    const float* w_x  = (const float*)d_in[1];
    const float* b_x  = (const float*)d_in[2];
    const float* w_h  = (const float*)d_in[3];
    const float* b_h  = (const float*)d_in[4];
    const float* fc_w = (const float*)d_in[5];
    const float* fc_b = (const float*)d_in[6];
    float* out = (float*)d_out;

    cudaFuncSetAttribute(gx_kernel,  cudaFuncAttributeMaxDynamicSharedMemorySize, GSM_TOT);
    cudaFuncSetAttribute(gru_kernel, cudaFuncAttributeMaxDynamicSharedMemorySize, SM_TOT);

    gx_kernel<<<dim3(32, TT), 256, GSM_TOT>>>(x, w_x);
    gru_kernel<<<128, 256, SM_TOT>>>(w_h, b_h, b_x, fc_w, fc_b, out);
}